// round 1
// baseline (speedup 1.0000x reference)
#include <cuda_runtime.h>
#include <cuda_bf16.h>

namespace {
constexpr int kNUser = 50000;
constexpr int kNItem = 30000;
constexpr int kN     = 80000;      // total nodes
constexpr int kE     = 1000000;    // 2 * NNZ symmetric edges
constexpr int kD     = 64;
constexpr int kF     = 4;
constexpr int kd     = 16;         // kD / kF
}

// ---------------- device scratch (static, no allocation) ----------------
__device__ float g_A[kE * kF];        // routing logits
__device__ float g_normA[kE * kF];    // softmax(A)
__device__ float g_buf0[kN * kD];     // ego ping
__device__ float g_buf1[kN * kD];     // ego pong
__device__ float g_sum[kN * kD];      // running sum of layer embeddings
__device__ float g_Tn[kN * kD];       // tanh(normalized tail chunks), per layer
__device__ float g_dinv[kN * kF];     // 1/sqrt(degree-weight)
__device__ float g_hinv[kN * kF];     // 1/||factor_emb chunk||
__device__ int   g_ptr[kN + 1];       // CSR row pointers (by head)
__device__ int   g_cnt[kN];           // histogram / fill counters
__device__ int   g_csr_t[kE];         // tail node per CSR slot
__device__ int   g_csr_e[kE];         // original edge id per CSR slot

// ---------------- init ----------------
__global__ void k_init_A() {
    int i = blockIdx.x * blockDim.x + threadIdx.x;   // one float4 row per edge
    if (i >= kE) return;
    reinterpret_cast<float4*>(g_A)[i]     = make_float4(1.f, 1.f, 1.f, 1.f);
    reinterpret_cast<float4*>(g_normA)[i] = make_float4(.25f, .25f, .25f, .25f);
}

__global__ void k_init_ego(const float* __restrict__ user, const float* __restrict__ item) {
    int i = blockIdx.x * blockDim.x + threadIdx.x;
    if (i >= kN * kD) return;
    float v = (i < kNUser * kD) ? user[i] : item[i - kNUser * kD];
    g_buf0[i] = v;
    g_sum[i]  = v;
}

__global__ void k_zero_cnt() {
    int i = blockIdx.x * blockDim.x + threadIdx.x;
    if (i < kN) g_cnt[i] = 0;
}

// ---------------- CSR build ----------------
__global__ void k_count(const int* __restrict__ h) {
    int e = blockIdx.x * blockDim.x + threadIdx.x;
    if (e >= kE) return;
    atomicAdd(&g_cnt[h[e]], 1);
}

// single-block exclusive scan of g_cnt -> g_ptr; zeroes g_cnt for reuse
__global__ void k_scan() {
    __shared__ int wsum[32];
    __shared__ int tot_s;
    const int lane = threadIdx.x & 31;
    const int wrp  = threadIdx.x >> 5;
    int carry = 0;
    for (int base = 0; base < kN; base += 1024) {
        int i = base + (int)threadIdx.x;
        int v = (i < kN) ? g_cnt[i] : 0;
        int x = v;
        #pragma unroll
        for (int o = 1; o < 32; o <<= 1) {
            int y = __shfl_up_sync(0xffffffffu, x, o);
            if (lane >= o) x += y;
        }
        if (lane == 31) wsum[wrp] = x;
        __syncthreads();
        if (wrp == 0) {
            int s  = wsum[lane];
            int xs = s;
            #pragma unroll
            for (int o = 1; o < 32; o <<= 1) {
                int y = __shfl_up_sync(0xffffffffu, xs, o);
                if (lane >= o) xs += y;
            }
            wsum[lane] = xs - s;          // exclusive warp offset
            if (lane == 31) tot_s = xs;   // chunk total
        }
        __syncthreads();
        int ex = carry + wsum[wrp] + (x - v);
        if (i < kN) { g_ptr[i] = ex; g_cnt[i] = 0; }
        carry += tot_s;
        __syncthreads();
    }
    if (threadIdx.x == 0) g_ptr[kN] = carry;
}

__global__ void k_fill(const int* __restrict__ h, const int* __restrict__ t) {
    int e = blockIdx.x * blockDim.x + threadIdx.x;
    if (e >= kE) return;
    int hn   = h[e];
    int slot = g_ptr[hn] + atomicAdd(&g_cnt[hn], 1);
    g_csr_t[slot] = t[e];
    g_csr_e[slot] = e;
}

// ---------------- per-layer: tanh(normalized tail chunks) ----------------
__global__ void k_tail(int sel) {
    const float* ego = sel ? g_buf1 : g_buf0;
    int i = blockIdx.x * blockDim.x + threadIdx.x;   // (node, factor)
    if (i >= kN * kF) return;
    const float4* src = reinterpret_cast<const float4*>(ego) + i * 4;
    float4 v0 = src[0], v1 = src[1], v2 = src[2], v3 = src[3];
    float ss = v0.x*v0.x + v0.y*v0.y + v0.z*v0.z + v0.w*v0.w
             + v1.x*v1.x + v1.y*v1.y + v1.z*v1.z + v1.w*v1.w
             + v2.x*v2.x + v2.y*v2.y + v2.z*v2.z + v2.w*v2.w
             + v3.x*v3.x + v3.y*v3.y + v3.z*v3.z + v3.w*v3.w;
    float inv = 1.0f / fmaxf(sqrtf(ss), 1e-12f);
    float4* dst = reinterpret_cast<float4*>(g_Tn) + i * 4;
    dst[0] = make_float4(tanhf(v0.x*inv), tanhf(v0.y*inv), tanhf(v0.z*inv), tanhf(v0.w*inv));
    dst[1] = make_float4(tanhf(v1.x*inv), tanhf(v1.y*inv), tanhf(v1.z*inv), tanhf(v1.w*inv));
    dst[2] = make_float4(tanhf(v2.x*inv), tanhf(v2.y*inv), tanhf(v2.z*inv), tanhf(v2.w*inv));
    dst[3] = make_float4(tanhf(v3.x*inv), tanhf(v3.y*inv), tanhf(v3.z*inv), tanhf(v3.w*inv));
}

// ---------------- per-iter: degree normalization ----------------
__global__ void k_dinv() {
    int n = blockIdx.x * blockDim.x + threadIdx.x;
    if (n >= kN) return;
    int s = g_ptr[n], e = g_ptr[n + 1];
    float4 acc = make_float4(0.f, 0.f, 0.f, 0.f);
    for (int j = s; j < e; j++) {
        float4 v = reinterpret_cast<const float4*>(g_normA)[g_csr_e[j]];
        acc.x += v.x; acc.y += v.y; acc.z += v.z; acc.w += v.w;
    }
    float4 di;
    di.x = rsqrtf(fmaxf(acc.x, 1e-8f));
    di.y = rsqrtf(fmaxf(acc.y, 1e-8f));
    di.z = rsqrtf(fmaxf(acc.z, 1e-8f));
    di.w = rsqrtf(fmaxf(acc.w, 1e-8f));
    reinterpret_cast<float4*>(g_dinv)[n] = di;
}

// ---------------- per-iter: message passing (+ head inv-norm) ----------------
// one warp per node; lane covers dims [lane] and [lane+32]
__global__ void k_mp(int sel_in, int sel_out) {
    const float* ego = sel_in ? g_buf1 : g_buf0;
    float* fe        = sel_out ? g_buf1 : g_buf0;
    int w = (blockIdx.x * blockDim.x + threadIdx.x) >> 5;
    if (w >= kN) return;
    const int lane = threadIdx.x & 31;
    const int f1 = lane >> 4;   // 0 or 1
    const int f2 = f1 + 2;      // 2 or 3
    int s = g_ptr[w], e = g_ptr[w + 1];
    float acc0 = 0.f, acc1 = 0.f;
    for (int j = s; j < e; j++) {
        int eid = g_csr_e[j];
        int tn  = g_csr_t[j];
        float wv = 0.f;
        if (lane < 4) wv = g_normA[eid * 4 + lane] * g_dinv[tn * 4 + lane];
        float w1 = __shfl_sync(0xffffffffu, wv, f1);
        float w2 = __shfl_sync(0xffffffffu, wv, f2);
        acc0 += w1 * ego[tn * kD + lane];
        acc1 += w2 * ego[tn * kD + lane + 32];
    }
    acc0 *= g_dinv[w * 4 + f1];
    acc1 *= g_dinv[w * 4 + f2];
    float ss0 = acc0 * acc0, ss1 = acc1 * acc1;
    #pragma unroll
    for (int o = 8; o >= 1; o >>= 1) {        // reduce within 16-lane groups
        ss0 += __shfl_xor_sync(0xffffffffu, ss0, o);
        ss1 += __shfl_xor_sync(0xffffffffu, ss1, o);
    }
    fe[w * kD + lane]      = acc0;
    fe[w * kD + lane + 32] = acc1;
    if ((lane & 15) == 0) {
        g_hinv[w * 4 + f1] = 1.0f / fmaxf(sqrtf(ss0), 1e-12f);
        g_hinv[w * 4 + f2] = 1.0f / fmaxf(sqrtf(ss1), 1e-12f);
    }
}

// ---------------- per-iter: routing update A += head_n . tanh(tail_n), fused softmax ----------------
// one warp per edge; lane covers dims [2*lane, 2*lane+1]; factor = lane>>3
__global__ void k_routing(int sel_fe, const int* __restrict__ hlist, const int* __restrict__ tlist) {
    const float* fe = sel_fe ? g_buf1 : g_buf0;
    int e = (blockIdx.x * blockDim.x + threadIdx.x) >> 5;
    if (e >= kE) return;
    const int lane = threadIdx.x & 31;
    int h = hlist[e];
    int t = tlist[e];
    float2 a = reinterpret_cast<const float2*>(fe)[h * 32 + lane];
    float2 b = reinterpret_cast<const float2*>(g_Tn)[t * 32 + lane];
    float p = a.x * b.x + a.y * b.y;
    #pragma unroll
    for (int o = 4; o >= 1; o >>= 1) p += __shfl_xor_sync(0xffffffffu, p, o);
    // lanes 0,8,16,24 hold factor dot products (f = lane>>3)
    float An = 0.f;
    const bool mem = (lane & 7) == 0;
    const int f = lane >> 3;
    if (mem) {
        An = g_A[e * 4 + f] + p * g_hinv[h * 4 + f];
    }
    // softmax across the 4 member lanes ({0,8,16,24} is closed under xor 8/16)
    float m = fmaxf(An, __shfl_xor_sync(0xffffffffu, An, 8));
    m = fmaxf(m, __shfl_xor_sync(0xffffffffu, m, 16));
    float ex = __expf(An - m);
    float sm = ex + __shfl_xor_sync(0xffffffffu, ex, 8);
    sm = sm + __shfl_xor_sync(0xffffffffu, sm, 16);
    if (mem) {
        g_A[e * 4 + f]     = An;
        g_normA[e * 4 + f] = ex / sm;
    }
}

// ---------------- accumulation / output ----------------
__global__ void k_accum(int sel_fe) {
    const float* fe = sel_fe ? g_buf1 : g_buf0;
    int i = blockIdx.x * blockDim.x + threadIdx.x;
    if (i < kN * kD) g_sum[i] += fe[i];
}

__global__ void k_final(int sel_fe, float* __restrict__ out) {
    const float* fe = sel_fe ? g_buf1 : g_buf0;
    int i = blockIdx.x * blockDim.x + threadIdx.x;
    if (i < kN * kD) out[i] = (g_sum[i] + fe[i]) * (1.0f / 3.0f);
}

// ---------------- host driver ----------------
extern "C" void kernel_launch(void* const* d_in, const int* in_sizes, int n_in,
                              void* d_out, int out_size) {
    const float* user = (const float*)d_in[0];
    const float* item = (const float*)d_in[1];
    const int*   hl   = (const int*)d_in[2];
    const int*   tl   = (const int*)d_in[3];
    float* out = (float*)d_out;

    const int TB = 256;
    // init
    k_init_A<<<(kE + TB - 1) / TB, TB>>>();
    k_init_ego<<<(kN * kD + TB - 1) / TB, TB>>>(user, item);
    k_zero_cnt<<<(kN + TB - 1) / TB, TB>>>();
    // CSR build
    k_count<<<(kE + TB - 1) / TB, TB>>>(hl);
    k_scan<<<1, 1024>>>();
    k_fill<<<(kE + TB - 1) / TB, TB>>>(hl, tl);

    // layer 0: in=buf0(0), out=buf1(1); layer 1: in=buf1(1), out=buf0(0)
    for (int layer = 0; layer < 2; layer++) {
        const int sin  = (layer == 0) ? 0 : 1;
        const int sout = 1 - sin;
        k_tail<<<(kN * kF + TB - 1) / TB, TB>>>(sin);
        for (int it = 0; it < 2; it++) {
            k_dinv<<<(kN + TB - 1) / TB, TB>>>();
            k_mp<<<(kN * 32 + TB - 1) / TB, TB>>>(sin, sout);
            // skip the final routing pass: its A update is never consumed
            if (!(layer == 1 && it == 1))
                k_routing<<<(kE * 32 + TB - 1) / TB, TB>>>(sout, hl, tl);
        }
        if (layer == 0)
            k_accum<<<(kN * kD + TB - 1) / TB, TB>>>(sout);
        else
            k_final<<<(kN * kD + TB - 1) / TB, TB>>>(sout, out);
    }
    (void)in_sizes; (void)n_in; (void)out_size;
}

// round 2
// speedup vs baseline: 1.5407x; 1.5407x over previous
#include <cuda_runtime.h>
#include <cuda_bf16.h>

namespace {
constexpr int kNUser = 50000;
constexpr int kN     = 80000;      // total nodes
constexpr int kE     = 1000000;    // 2 * NNZ symmetric edges
constexpr int kD     = 64;
}

// ---------------- device scratch (static, no allocation) ----------------
__device__ float g_A[kE * 4];         // routing logits, CSR-slot order
__device__ float g_normA[kE * 4];     // softmax(A), CSR-slot order
__device__ float g_buf0[kN * kD];     // ego ping
__device__ float g_buf1[kN * kD];     // ego pong
__device__ float g_Tn[kN * kD];       // tanh(normalized tail chunks), per layer
__device__ float g_dinvA[kN * 4];     // 1/sqrt(degree-weight), ping
__device__ float g_dinvB[kN * 4];     // pong
__device__ int   g_ptr[kN + 1];       // CSR row pointers (by head)
__device__ int   g_cnt[kN];           // histogram / fill counters
__device__ int   g_csr_t[kE];         // tail node per CSR slot

// ---------------- init ----------------
__global__ void k_init_ego(const float* __restrict__ user, const float* __restrict__ item) {
    int i = blockIdx.x * blockDim.x + threadIdx.x;
    if (i >= kN * kD) return;
    g_buf0[i] = (i < kNUser * kD) ? user[i] : item[i - kNUser * kD];
}

__global__ void k_zero_cnt() {
    int i = blockIdx.x * blockDim.x + threadIdx.x;
    if (i < kN) g_cnt[i] = 0;
}

// ---------------- CSR build ----------------
__global__ void k_count(const int* __restrict__ h) {
    int e = blockIdx.x * blockDim.x + threadIdx.x;
    if (e >= kE) return;
    atomicAdd(&g_cnt[h[e]], 1);
}

// single-block exclusive scan of g_cnt -> g_ptr; zeroes g_cnt for reuse
__global__ void k_scan() {
    __shared__ int wsum[32];
    __shared__ int tot_s;
    const int lane = threadIdx.x & 31;
    const int wrp  = threadIdx.x >> 5;
    int carry = 0;
    for (int base = 0; base < kN; base += 1024) {
        int i = base + (int)threadIdx.x;
        int v = (i < kN) ? g_cnt[i] : 0;
        int x = v;
        #pragma unroll
        for (int o = 1; o < 32; o <<= 1) {
            int y = __shfl_up_sync(0xffffffffu, x, o);
            if (lane >= o) x += y;
        }
        if (lane == 31) wsum[wrp] = x;
        __syncthreads();
        if (wrp == 0) {
            int s  = wsum[lane];
            int xs = s;
            #pragma unroll
            for (int o = 1; o < 32; o <<= 1) {
                int y = __shfl_up_sync(0xffffffffu, xs, o);
                if (lane >= o) xs += y;
            }
            wsum[lane] = xs - s;
            if (lane == 31) tot_s = xs;
        }
        __syncthreads();
        int ex = carry + wsum[wrp] + (x - v);
        if (i < kN) { g_ptr[i] = ex; g_cnt[i] = 0; }
        carry += tot_s;
        __syncthreads();
    }
    if (threadIdx.x == 0) g_ptr[kN] = carry;
}

// fill CSR + initialize A=1, normA=0.25 in slot order
__global__ void k_fill(const int* __restrict__ h, const int* __restrict__ t) {
    int e = blockIdx.x * blockDim.x + threadIdx.x;
    if (e >= kE) return;
    int hn   = h[e];
    int slot = g_ptr[hn] + atomicAdd(&g_cnt[hn], 1);
    g_csr_t[slot] = t[e];
    reinterpret_cast<float4*>(g_A)[slot]     = make_float4(1.f, 1.f, 1.f, 1.f);
    reinterpret_cast<float4*>(g_normA)[slot] = make_float4(.25f, .25f, .25f, .25f);
}

// initial dinv: normA = 0.25 everywhere -> dval = 0.25 * deg
__global__ void k_dinv0() {
    int n = blockIdx.x * blockDim.x + threadIdx.x;
    if (n >= kN) return;
    float dval = 0.25f * (float)(g_ptr[n + 1] - g_ptr[n]);
    float di = rsqrtf(fmaxf(dval, 1e-8f));
    reinterpret_cast<float4*>(g_dinvA)[n] = make_float4(di, di, di, di);
}

// ---------------- per-layer: tanh(normalized tail chunks) ----------------
__global__ void k_tail(int sel) {
    const float* ego = sel ? g_buf1 : g_buf0;
    int i = blockIdx.x * blockDim.x + threadIdx.x;   // (node, factor)
    if (i >= kN * 4) return;
    const float4* src = reinterpret_cast<const float4*>(ego) + i * 4;
    float4 v0 = src[0], v1 = src[1], v2 = src[2], v3 = src[3];
    float ss = v0.x*v0.x + v0.y*v0.y + v0.z*v0.z + v0.w*v0.w
             + v1.x*v1.x + v1.y*v1.y + v1.z*v1.z + v1.w*v1.w
             + v2.x*v2.x + v2.y*v2.y + v2.z*v2.z + v2.w*v2.w
             + v3.x*v3.x + v3.y*v3.y + v3.z*v3.z + v3.w*v3.w;
    float inv = 1.0f / fmaxf(sqrtf(ss), 1e-12f);
    float4* dst = reinterpret_cast<float4*>(g_Tn) + i * 4;
    dst[0] = make_float4(tanhf(v0.x*inv), tanhf(v0.y*inv), tanhf(v0.z*inv), tanhf(v0.w*inv));
    dst[1] = make_float4(tanhf(v1.x*inv), tanhf(v1.y*inv), tanhf(v1.z*inv), tanhf(v1.w*inv));
    dst[2] = make_float4(tanhf(v2.x*inv), tanhf(v2.y*inv), tanhf(v2.z*inv), tanhf(v2.w*inv));
    dst[3] = make_float4(tanhf(v3.x*inv), tanhf(v3.y*inv), tanhf(v3.z*inv), tanhf(v3.w*inv));
}

// ---------------- fused iteration: mp + head-norm + routing + softmax + next dinv ----------------
// one warp per node. lane covers dims [lane] (factor f1 = lane>>4) and
// [lane+32] (factor f2 = f1+2).
// mode: 0 = normal (write fe), 2 = final (write out = (input + prev_layer + fe)/3)
__global__ void __launch_bounds__(256) k_fused(
        int sel_in, int do_rout, int dsel, int mode,
        const float* __restrict__ user, const float* __restrict__ item,
        float* __restrict__ out)
{
    int w = blockIdx.x * 8 + (threadIdx.x >> 5);
    if (w >= kN) return;
    const int lane = threadIdx.x & 31;
    const int f1 = lane >> 4;

    const float*  ego   = sel_in ? g_buf1 : g_buf0;
    float*        fe    = sel_in ? g_buf0 : g_buf1;
    const float4* dinvC = reinterpret_cast<const float4*>(dsel ? g_dinvB : g_dinvA);
    float4*       dinvN = reinterpret_cast<float4*>(dsel ? g_dinvA : g_dinvB);
    const float4* normA = reinterpret_cast<const float4*>(g_normA);
    float4*       normAo= reinterpret_cast<float4*>(g_normA);
    float4*       Ap    = reinterpret_cast<float4*>(g_A);

    const int s = g_ptr[w], e = g_ptr[w + 1];

    // ---- message passing ----
    float acc0 = 0.f, acc1 = 0.f;
    for (int base = s; base < e; base += 32) {
        int j = base + lane;
        bool valid = j < e;
        int t = valid ? g_csr_t[j] : 0;
        float4 na = valid ? normA[j] : make_float4(0.f, 0.f, 0.f, 0.f);
        float4 dv = dinvC[t];
        float wx = na.x * dv.x, wy = na.y * dv.y;
        float wz = na.z * dv.z, ww = na.w * dv.w;
        int cnt = min(32, e - base);
        for (int k = 0; k < cnt; k++) {
            int   tk = __shfl_sync(0xffffffffu, t,  k);
            float ax = __shfl_sync(0xffffffffu, wx, k);
            float ay = __shfl_sync(0xffffffffu, wy, k);
            float az = __shfl_sync(0xffffffffu, wz, k);
            float aw = __shfl_sync(0xffffffffu, ww, k);
            float w1 = f1 ? ay : ax;
            float w2 = f1 ? aw : az;
            acc0 += w1 * ego[tk * kD + lane];
            acc1 += w2 * ego[tk * kD + lane + 32];
        }
    }
    {
        float4 dh = dinvC[w];
        acc0 *= (f1 ? dh.y : dh.x);
        acc1 *= (f1 ? dh.w : dh.z);
    }

    if (mode == 2) {
        // final: out = (input_ego + prev_layer(ego buf) + fe)/3
        const float* inp = (w < kNUser) ? user + w * kD : item + (w - kNUser) * kD;
        out[w * kD + lane]      = (inp[lane]      + ego[w * kD + lane]      + acc0) * (1.0f / 3.0f);
        out[w * kD + lane + 32] = (inp[lane + 32] + ego[w * kD + lane + 32] + acc1) * (1.0f / 3.0f);
        return;
    }

    fe[w * kD + lane]      = acc0;
    fe[w * kD + lane + 32] = acc1;

    if (!do_rout) return;

    // ---- head inverse norms (per 16-lane group = one factor) ----
    float ss0 = acc0 * acc0, ss1 = acc1 * acc1;
    #pragma unroll
    for (int o = 8; o >= 1; o >>= 1) {
        ss0 += __shfl_xor_sync(0xffffffffu, ss0, o);
        ss1 += __shfl_xor_sync(0xffffffffu, ss1, o);
    }
    const float hA = 1.0f / fmaxf(sqrtf(ss0), 1e-12f);  // factor f1
    const float hB = 1.0f / fmaxf(sqrtf(ss1), 1e-12f);  // factor f1+2

    // ---- routing + fused softmax + dval accumulation ----
    float4 dval = make_float4(0.f, 0.f, 0.f, 0.f);
    for (int base = s; base < e; base += 32) {
        int j = base + lane;
        bool valid = j < e;
        int t = valid ? g_csr_t[j] : 0;
        float4 An = valid ? Ap[j] : make_float4(0.f, 0.f, 0.f, 0.f);
        int cnt = min(32, e - base);
        for (int k = 0; k < cnt; k++) {
            int tk = __shfl_sync(0xffffffffu, t, k);
            float p0 = acc0 * g_Tn[tk * kD + lane];
            float p1 = acc1 * g_Tn[tk * kD + lane + 32];
            #pragma unroll
            for (int o = 8; o >= 1; o >>= 1) {
                p0 += __shfl_xor_sync(0xffffffffu, p0, o);
                p1 += __shfl_xor_sync(0xffffffffu, p1, o);
            }
            float q0 = p0 * hA;                           // factor f1
            float q1 = p1 * hB;                           // factor f1+2
            float q0o = __shfl_xor_sync(0xffffffffu, q0, 16);  // factor 1-f1
            float q1o = __shfl_xor_sync(0xffffffffu, q1, 16);  // factor 3-f1
            if (lane == k) {
                An.x += f1 ? q0o : q0;
                An.y += f1 ? q0  : q0o;
                An.z += f1 ? q1o : q1;
                An.w += f1 ? q1  : q1o;
            }
        }
        // per-lane softmax over its own edge's 4 factors (vectorized across 32 edges)
        float m = fmaxf(fmaxf(An.x, An.y), fmaxf(An.z, An.w));
        float e0 = __expf(An.x - m), e1 = __expf(An.y - m);
        float e2 = __expf(An.z - m), e3 = __expf(An.w - m);
        float inv = 1.0f / (e0 + e1 + e2 + e3);
        if (valid) {
            Ap[j]     = An;
            float4 nA = make_float4(e0 * inv, e1 * inv, e2 * inv, e3 * inv);
            normAo[j] = nA;
            dval.x += nA.x; dval.y += nA.y; dval.z += nA.z; dval.w += nA.w;
        }
    }
    // reduce dval across warp -> next iteration's dinv for this node
    #pragma unroll
    for (int o = 16; o >= 1; o >>= 1) {
        dval.x += __shfl_xor_sync(0xffffffffu, dval.x, o);
        dval.y += __shfl_xor_sync(0xffffffffu, dval.y, o);
        dval.z += __shfl_xor_sync(0xffffffffu, dval.z, o);
        dval.w += __shfl_xor_sync(0xffffffffu, dval.w, o);
    }
    if (lane == 0) {
        dinvN[w] = make_float4(rsqrtf(fmaxf(dval.x, 1e-8f)),
                               rsqrtf(fmaxf(dval.y, 1e-8f)),
                               rsqrtf(fmaxf(dval.z, 1e-8f)),
                               rsqrtf(fmaxf(dval.w, 1e-8f)));
    }
}

// ---------------- host driver ----------------
extern "C" void kernel_launch(void* const* d_in, const int* in_sizes, int n_in,
                              void* d_out, int out_size) {
    const float* user = (const float*)d_in[0];
    const float* item = (const float*)d_in[1];
    const int*   hl   = (const int*)d_in[2];
    const int*   tl   = (const int*)d_in[3];
    float* out = (float*)d_out;

    const int TB = 256;
    k_init_ego<<<(kN * kD + TB - 1) / TB, TB>>>(user, item);
    k_zero_cnt<<<(kN + TB - 1) / TB, TB>>>();
    k_count<<<(kE + TB - 1) / TB, TB>>>(hl);
    k_scan<<<1, 1024>>>();
    k_fill<<<(kE + TB - 1) / TB, TB>>>(hl, tl);
    k_dinv0<<<(kN + TB - 1) / TB, TB>>>();

    const int FG = (kN + 7) / 8;   // 8 warps / block
    // layer 0: ego=buf0 -> fe=buf1 (both iterations use layer input ego)
    k_tail<<<(kN * 4 + TB - 1) / TB, TB>>>(0);
    k_fused<<<FG, TB>>>(0, 1, 0, 0, user, item, out);  // it0: dinv A->B
    k_fused<<<FG, TB>>>(0, 1, 1, 0, user, item, out);  // it1: dinv B->A
    // layer 1: ego=buf1 -> fe=buf0
    k_tail<<<(kN * 4 + TB - 1) / TB, TB>>>(1);
    k_fused<<<FG, TB>>>(1, 1, 0, 0, user, item, out);  // it0: dinv A->B
    k_fused<<<FG, TB>>>(1, 0, 1, 2, user, item, out);  // it1: final, no routing
    (void)in_sizes; (void)n_in; (void)out_size;
}

// round 3
// speedup vs baseline: 1.6901x; 1.0970x over previous
#include <cuda_runtime.h>
#include <cuda_bf16.h>

namespace {
constexpr int kNUser = 50000;
constexpr int kN     = 80000;      // total nodes
constexpr int kE     = 1000000;    // 2 * NNZ symmetric edges
constexpr int kD     = 64;
constexpr int kChunk = 1024;
constexpr int kNChunk = (kN + kChunk - 1) / kChunk;   // 79
}

// ---------------- device scratch (static, no allocation) ----------------
__device__ float g_A[kE * 4];         // routing logits, CSR-slot order
__device__ float g_normA[kE * 4];     // softmax(A), CSR-slot order
__device__ float g_buf0[kN * kD];     // ego ping
__device__ float g_buf1[kN * kD];     // ego pong
__device__ float g_Tn[kN * kD];       // tanh(normalized tail chunks), per layer
__device__ float g_dinvA[kN * 4];     // 1/sqrt(degree-weight), ping
__device__ float g_dinvB[kN * 4];     // pong
__device__ int   g_ptr[kN + 1];       // CSR row pointers (by head)
__device__ int   g_cnt[kN];           // histogram / fill counters
__device__ int   g_csr_t[kE];         // tail node per CSR slot
__device__ int   g_bsum[kNChunk];     // per-chunk sums for multi-block scan

// ---------------- init ----------------
__global__ void k_init_ego(const float* __restrict__ user, const float* __restrict__ item) {
    int i = blockIdx.x * blockDim.x + threadIdx.x;
    if (i >= kN * kD) return;
    g_buf0[i] = (i < kNUser * kD) ? user[i] : item[i - kNUser * kD];
}

__global__ void k_zero_cnt() {
    int i = blockIdx.x * blockDim.x + threadIdx.x;
    if (i < kN) g_cnt[i] = 0;
}

// ---------------- CSR build ----------------
__global__ void k_count(const int* __restrict__ h) {
    int e = blockIdx.x * blockDim.x + threadIdx.x;
    if (e >= kE) return;
    atomicAdd(&g_cnt[h[e]], 1);
}

// ---- multi-block exclusive scan: reduce -> scan block sums -> chunk scan ----
__global__ void k_chunk_reduce() {            // kNChunk blocks x 256
    __shared__ int wsum[8];
    const int lane = threadIdx.x & 31, wrp = threadIdx.x >> 5;
    int base = blockIdx.x * kChunk + (int)threadIdx.x * 4;
    int s = 0;
    #pragma unroll
    for (int k = 0; k < 4; k++) { int i = base + k; if (i < kN) s += g_cnt[i]; }
    #pragma unroll
    for (int o = 16; o >= 1; o >>= 1) s += __shfl_xor_sync(0xffffffffu, s, o);
    if (lane == 0) wsum[wrp] = s;
    __syncthreads();
    if (threadIdx.x == 0) {
        int t = 0;
        #pragma unroll
        for (int k = 0; k < 8; k++) t += wsum[k];
        g_bsum[blockIdx.x] = t;
    }
}

__global__ void k_bsum_scan() {               // 1 block x 32
    const int lane = threadIdx.x;
    int carry = 0;
    for (int base = 0; base < kNChunk; base += 32) {
        int i = base + lane;
        int v = (i < kNChunk) ? g_bsum[i] : 0;
        int x = v;
        #pragma unroll
        for (int o = 1; o < 32; o <<= 1) {
            int y = __shfl_up_sync(0xffffffffu, x, o);
            if (lane >= o) x += y;
        }
        if (i < kNChunk) g_bsum[i] = carry + x - v;     // exclusive
        carry += __shfl_sync(0xffffffffu, x, 31);
    }
    if (lane == 0) g_ptr[kN] = carry;
}

__global__ void k_chunk_scan() {              // kNChunk blocks x 256
    __shared__ int wsum[8];
    const int lane = threadIdx.x & 31, wrp = threadIdx.x >> 5;
    int base = blockIdx.x * kChunk + (int)threadIdx.x * 4;
    int v0 = 0, v1 = 0, v2 = 0, v3 = 0;
    if (base + 3 < kN) {
        int4 v = *reinterpret_cast<const int4*>(&g_cnt[base]);
        v0 = v.x; v1 = v.y; v2 = v.z; v3 = v.w;
    } else {
        if (base + 0 < kN) v0 = g_cnt[base + 0];
        if (base + 1 < kN) v1 = g_cnt[base + 1];
        if (base + 2 < kN) v2 = g_cnt[base + 2];
        if (base + 3 < kN) v3 = g_cnt[base + 3];
    }
    int tot = v0 + v1 + v2 + v3;
    int x = tot;
    #pragma unroll
    for (int o = 1; o < 32; o <<= 1) {
        int y = __shfl_up_sync(0xffffffffu, x, o);
        if (lane >= o) x += y;
    }
    if (lane == 31) wsum[wrp] = x;
    __syncthreads();
    if (wrp == 0 && lane < 8) {
        int s = wsum[lane], xs = s;
        #pragma unroll
        for (int o = 1; o < 8; o <<= 1) {
            int y = __shfl_up_sync(0xffu, xs, o);
            if (lane >= o) xs += y;
        }
        wsum[lane] = xs - s;
    }
    __syncthreads();
    int ex = g_bsum[blockIdx.x] + wsum[wrp] + (x - tot);
    if (base + 0 < kN) { g_ptr[base + 0] = ex;                g_cnt[base + 0] = 0; }
    if (base + 1 < kN) { g_ptr[base + 1] = ex + v0;           g_cnt[base + 1] = 0; }
    if (base + 2 < kN) { g_ptr[base + 2] = ex + v0 + v1;      g_cnt[base + 2] = 0; }
    if (base + 3 < kN) { g_ptr[base + 3] = ex + v0 + v1 + v2; g_cnt[base + 3] = 0; }
}

// fill CSR + initialize A=1, normA=0.25 in slot order
__global__ void k_fill(const int* __restrict__ h, const int* __restrict__ t) {
    int e = blockIdx.x * blockDim.x + threadIdx.x;
    if (e >= kE) return;
    int hn   = h[e];
    int slot = g_ptr[hn] + atomicAdd(&g_cnt[hn], 1);
    g_csr_t[slot] = t[e];
    reinterpret_cast<float4*>(g_A)[slot]     = make_float4(1.f, 1.f, 1.f, 1.f);
    reinterpret_cast<float4*>(g_normA)[slot] = make_float4(.25f, .25f, .25f, .25f);
}

// initial dinv: normA = 0.25 everywhere -> dval = 0.25 * deg
__global__ void k_dinv0() {
    int n = blockIdx.x * blockDim.x + threadIdx.x;
    if (n >= kN) return;
    float dval = 0.25f * (float)(g_ptr[n + 1] - g_ptr[n]);
    float di = rsqrtf(fmaxf(dval, 1e-8f));
    reinterpret_cast<float4*>(g_dinvA)[n] = make_float4(di, di, di, di);
}

// ---------------- per-layer: tanh(normalized tail chunks) ----------------
__global__ void k_tail(int sel) {
    const float* ego = sel ? g_buf1 : g_buf0;
    int i = blockIdx.x * blockDim.x + threadIdx.x;   // (node, factor)
    if (i >= kN * 4) return;
    const float4* src = reinterpret_cast<const float4*>(ego) + i * 4;
    float4 v0 = src[0], v1 = src[1], v2 = src[2], v3 = src[3];
    float ss = v0.x*v0.x + v0.y*v0.y + v0.z*v0.z + v0.w*v0.w
             + v1.x*v1.x + v1.y*v1.y + v1.z*v1.z + v1.w*v1.w
             + v2.x*v2.x + v2.y*v2.y + v2.z*v2.z + v2.w*v2.w
             + v3.x*v3.x + v3.y*v3.y + v3.z*v3.z + v3.w*v3.w;
    float inv = 1.0f / fmaxf(sqrtf(ss), 1e-12f);
    float4* dst = reinterpret_cast<float4*>(g_Tn) + i * 4;
    dst[0] = make_float4(tanhf(v0.x*inv), tanhf(v0.y*inv), tanhf(v0.z*inv), tanhf(v0.w*inv));
    dst[1] = make_float4(tanhf(v1.x*inv), tanhf(v1.y*inv), tanhf(v1.z*inv), tanhf(v1.w*inv));
    dst[2] = make_float4(tanhf(v2.x*inv), tanhf(v2.y*inv), tanhf(v2.z*inv), tanhf(v2.w*inv));
    dst[3] = make_float4(tanhf(v3.x*inv), tanhf(v3.y*inv), tanhf(v3.z*inv), tanhf(v3.w*inv));
}

// ---------------- fused iteration ----------------
// one warp per node; MP: smem-broadcast edge weights; routing: lane-per-edge
// with normalized head vector staged in smem.
__global__ void __launch_bounds__(256) k_fused(
        int sel_in, int do_rout, int dsel, int mode,
        const float* __restrict__ user, const float* __restrict__ item,
        float* __restrict__ out)
{
    __shared__ int    sm_t[8][32];
    __shared__ float4 sm_w[8][32];
    __shared__ float4 sm_h[8][16];      // normalized head (64 floats / warp)

    const int warp = threadIdx.x >> 5;
    const int lane = threadIdx.x & 31;
    int w = blockIdx.x * 8 + warp;
    if (w >= kN) return;
    const int f1 = lane >> 4;

    const float*  ego    = sel_in ? g_buf1 : g_buf0;
    float*        fe     = sel_in ? g_buf0 : g_buf1;
    const float4* dinvC  = reinterpret_cast<const float4*>(dsel ? g_dinvB : g_dinvA);
    float4*       dinvN  = reinterpret_cast<float4*>(dsel ? g_dinvA : g_dinvB);
    const float4* normA  = reinterpret_cast<const float4*>(g_normA);
    float4*       normAo = reinterpret_cast<float4*>(g_normA);
    float4*       Ap     = reinterpret_cast<float4*>(g_A);

    const int s = g_ptr[w], e = g_ptr[w + 1];

    // ---- message passing ----
    float acc0 = 0.f, acc1 = 0.f;
    for (int base = s; base < e; base += 32) {
        int j = base + lane;
        bool valid = j < e;
        int t = valid ? g_csr_t[j] : 0;
        float4 na = valid ? normA[j] : make_float4(0.f, 0.f, 0.f, 0.f);
        float4 dv = dinvC[t];
        sm_t[warp][lane] = t;
        sm_w[warp][lane] = make_float4(na.x * dv.x, na.y * dv.y, na.z * dv.z, na.w * dv.w);
        __syncwarp();
        int cnt = min(32, e - base);
        #pragma unroll 4
        for (int k = 0; k < cnt; k++) {
            int    tk = sm_t[warp][k];
            float4 w4 = sm_w[warp][k];
            acc0 += (f1 ? w4.y : w4.x) * ego[tk * kD + lane];
            acc1 += (f1 ? w4.w : w4.z) * ego[tk * kD + lane + 32];
        }
        __syncwarp();
    }
    {
        float4 dh = dinvC[w];
        acc0 *= (f1 ? dh.y : dh.x);
        acc1 *= (f1 ? dh.w : dh.z);
    }

    if (mode == 2) {
        // final: out = (input_ego + prev_layer(ego buf) + fe)/3
        const float* inp = (w < kNUser) ? user + w * kD : item + (w - kNUser) * kD;
        out[w * kD + lane]      = (inp[lane]      + ego[w * kD + lane]      + acc0) * (1.0f / 3.0f);
        out[w * kD + lane + 32] = (inp[lane + 32] + ego[w * kD + lane + 32] + acc1) * (1.0f / 3.0f);
        return;
    }

    fe[w * kD + lane]      = acc0;
    fe[w * kD + lane + 32] = acc1;

    if (!do_rout) return;

    // ---- head inverse norms (per 16-lane group = one factor) ----
    float ss0 = acc0 * acc0, ss1 = acc1 * acc1;
    #pragma unroll
    for (int o = 8; o >= 1; o >>= 1) {
        ss0 += __shfl_xor_sync(0xffffffffu, ss0, o);
        ss1 += __shfl_xor_sync(0xffffffffu, ss1, o);
    }
    const float hA = 1.0f / fmaxf(sqrtf(ss0), 1e-12f);  // factor f1
    const float hB = 1.0f / fmaxf(sqrtf(ss1), 1e-12f);  // factor f1+2

    // stage normalized head into smem (dim order 0..63)
    {
        float* hp = reinterpret_cast<float*>(&sm_h[warp][0]);
        hp[lane]      = acc0 * hA;
        hp[lane + 32] = acc1 * hB;
    }
    __syncwarp();

    // ---- routing: lane-per-edge, fused softmax + dval accumulation ----
    float4 dval = make_float4(0.f, 0.f, 0.f, 0.f);
    for (int base = s; base < e; base += 32) {
        int j = base + lane;
        if (j < e) {
            int t = g_csr_t[j];
            const float4* tn = reinterpret_cast<const float4*>(g_Tn + t * kD);
            float q0 = 0.f, q1 = 0.f, q2 = 0.f, q3 = 0.f;
            #pragma unroll
            for (int c = 0; c < 4; c++) {
                float4 h0 = sm_h[warp][c],      t0 = tn[c];
                float4 h1 = sm_h[warp][4 + c],  t1 = tn[4 + c];
                float4 h2 = sm_h[warp][8 + c],  t2 = tn[8 + c];
                float4 h3 = sm_h[warp][12 + c], t3 = tn[12 + c];
                q0 += h0.x*t0.x + h0.y*t0.y + h0.z*t0.z + h0.w*t0.w;
                q1 += h1.x*t1.x + h1.y*t1.y + h1.z*t1.z + h1.w*t1.w;
                q2 += h2.x*t2.x + h2.y*t2.y + h2.z*t2.z + h2.w*t2.w;
                q3 += h3.x*t3.x + h3.y*t3.y + h3.z*t3.z + h3.w*t3.w;
            }
            float4 An = Ap[j];
            An.x += q0; An.y += q1; An.z += q2; An.w += q3;
            float m  = fmaxf(fmaxf(An.x, An.y), fmaxf(An.z, An.w));
            float e0 = __expf(An.x - m), e1 = __expf(An.y - m);
            float e2 = __expf(An.z - m), e3 = __expf(An.w - m);
            float inv = 1.0f / (e0 + e1 + e2 + e3);
            Ap[j] = An;
            float4 nA = make_float4(e0 * inv, e1 * inv, e2 * inv, e3 * inv);
            normAo[j] = nA;
            dval.x += nA.x; dval.y += nA.y; dval.z += nA.z; dval.w += nA.w;
        }
    }
    // reduce dval across warp -> next iteration's dinv for this node
    #pragma unroll
    for (int o = 16; o >= 1; o >>= 1) {
        dval.x += __shfl_xor_sync(0xffffffffu, dval.x, o);
        dval.y += __shfl_xor_sync(0xffffffffu, dval.y, o);
        dval.z += __shfl_xor_sync(0xffffffffu, dval.z, o);
        dval.w += __shfl_xor_sync(0xffffffffu, dval.w, o);
    }
    if (lane == 0) {
        dinvN[w] = make_float4(rsqrtf(fmaxf(dval.x, 1e-8f)),
                               rsqrtf(fmaxf(dval.y, 1e-8f)),
                               rsqrtf(fmaxf(dval.z, 1e-8f)),
                               rsqrtf(fmaxf(dval.w, 1e-8f)));
    }
}

// ---------------- host driver ----------------
extern "C" void kernel_launch(void* const* d_in, const int* in_sizes, int n_in,
                              void* d_out, int out_size) {
    const float* user = (const float*)d_in[0];
    const float* item = (const float*)d_in[1];
    const int*   hl   = (const int*)d_in[2];
    const int*   tl   = (const int*)d_in[3];
    float* out = (float*)d_out;

    const int TB = 256;
    k_init_ego<<<(kN * kD + TB - 1) / TB, TB>>>(user, item);
    k_zero_cnt<<<(kN + TB - 1) / TB, TB>>>();
    k_count<<<(kE + TB - 1) / TB, TB>>>(hl);
    k_chunk_reduce<<<kNChunk, TB>>>();
    k_bsum_scan<<<1, 32>>>();
    k_chunk_scan<<<kNChunk, TB>>>();
    k_fill<<<(kE + TB - 1) / TB, TB>>>(hl, tl);
    k_dinv0<<<(kN + TB - 1) / TB, TB>>>();

    const int FG = (kN + 7) / 8;   // 8 warps / block
    // layer 0: ego=buf0 -> fe=buf1
    k_tail<<<(kN * 4 + TB - 1) / TB, TB>>>(0);
    k_fused<<<FG, TB>>>(0, 1, 0, 0, user, item, out);  // it0: dinv A->B
    k_fused<<<FG, TB>>>(0, 1, 1, 0, user, item, out);  // it1: dinv B->A
    // layer 1: ego=buf1 -> fe=buf0
    k_tail<<<(kN * 4 + TB - 1) / TB, TB>>>(1);
    k_fused<<<FG, TB>>>(1, 1, 0, 0, user, item, out);  // it0: dinv A->B
    k_fused<<<FG, TB>>>(1, 0, 1, 2, user, item, out);  // it1: final, no routing
    (void)in_sizes; (void)n_in; (void)out_size;
}

// round 5
// speedup vs baseline: 1.7061x; 1.0095x over previous
#include <cuda_runtime.h>
#include <cuda_bf16.h>

namespace {
constexpr int kNUser = 50000;
constexpr int kN     = 80000;      // total nodes
constexpr int kE     = 1000000;    // 2 * NNZ symmetric edges
constexpr int kD     = 64;
constexpr int kChunk = 1024;
constexpr int kNChunk = (kN + kChunk - 1) / kChunk;   // 79
}

// ---------------- device scratch (static, no allocation) ----------------
__device__ float g_A[kE * 4];         // routing logits, CSR-slot order
__device__ float g_normA[kE * 4];     // softmax(A), CSR-slot order
__device__ float g_buf0[kN * kD];     // ego ping
__device__ float g_buf1[kN * kD];     // ego pong
__device__ float g_egoS0[kN * kD];    // ego prescaled by current dinv (ping)
__device__ float g_egoS1[kN * kD];    // (pong)
__device__ float g_Tn[kN * kD];       // tanh(normalized tail chunks), per layer
__device__ float g_dinvA[kN * 4];     // 1/sqrt(degree-weight), ping
__device__ float g_dinvB[kN * 4];     // pong
__device__ int   g_ptr[kN + 1];       // CSR row pointers (by head)
__device__ int   g_cnt[kN];           // histogram / fill counters
__device__ int   g_csr_t[kE];         // tail node per CSR slot
__device__ int   g_bsum[kNChunk];     // per-chunk sums for multi-block scan

// ---------------- init ----------------
__global__ void k_init_ego(const float* __restrict__ user, const float* __restrict__ item) {
    int i = blockIdx.x * blockDim.x + threadIdx.x;
    if (i >= kN * kD) return;
    g_buf0[i] = (i < kNUser * kD) ? user[i] : item[i - kNUser * kD];
}

__global__ void k_zero_cnt() {
    int i = blockIdx.x * blockDim.x + threadIdx.x;
    if (i < kN) g_cnt[i] = 0;
}

// ---------------- CSR build ----------------
__global__ void k_count(const int* __restrict__ h) {
    int e = blockIdx.x * blockDim.x + threadIdx.x;
    if (e >= kE) return;
    atomicAdd(&g_cnt[h[e]], 1);
}

__global__ void k_chunk_reduce() {            // kNChunk blocks x 256
    __shared__ int wsum[8];
    const int lane = threadIdx.x & 31, wrp = threadIdx.x >> 5;
    int base = blockIdx.x * kChunk + (int)threadIdx.x * 4;
    int s = 0;
    #pragma unroll
    for (int k = 0; k < 4; k++) { int i = base + k; if (i < kN) s += g_cnt[i]; }
    #pragma unroll
    for (int o = 16; o >= 1; o >>= 1) s += __shfl_xor_sync(0xffffffffu, s, o);
    if (lane == 0) wsum[wrp] = s;
    __syncthreads();
    if (threadIdx.x == 0) {
        int t = 0;
        #pragma unroll
        for (int k = 0; k < 8; k++) t += wsum[k];
        g_bsum[blockIdx.x] = t;
    }
}

__global__ void k_bsum_scan() {               // 1 block x 32
    const int lane = threadIdx.x;
    int carry = 0;
    for (int base = 0; base < kNChunk; base += 32) {
        int i = base + lane;
        int v = (i < kNChunk) ? g_bsum[i] : 0;
        int x = v;
        #pragma unroll
        for (int o = 1; o < 32; o <<= 1) {
            int y = __shfl_up_sync(0xffffffffu, x, o);
            if (lane >= o) x += y;
        }
        if (i < kNChunk) g_bsum[i] = carry + x - v;     // exclusive
        carry += __shfl_sync(0xffffffffu, x, 31);
    }
    if (lane == 0) g_ptr[kN] = carry;
}

__global__ void k_chunk_scan() {              // kNChunk blocks x 256
    __shared__ int wsum[8];
    const int lane = threadIdx.x & 31, wrp = threadIdx.x >> 5;
    int base = blockIdx.x * kChunk + (int)threadIdx.x * 4;
    int v0 = 0, v1 = 0, v2 = 0, v3 = 0;
    if (base + 3 < kN) {
        int4 v = *reinterpret_cast<const int4*>(&g_cnt[base]);
        v0 = v.x; v1 = v.y; v2 = v.z; v3 = v.w;
    } else {
        if (base + 0 < kN) v0 = g_cnt[base + 0];
        if (base + 1 < kN) v1 = g_cnt[base + 1];
        if (base + 2 < kN) v2 = g_cnt[base + 2];
        if (base + 3 < kN) v3 = g_cnt[base + 3];
    }
    int tot = v0 + v1 + v2 + v3;
    int x = tot;
    #pragma unroll
    for (int o = 1; o < 32; o <<= 1) {
        int y = __shfl_up_sync(0xffffffffu, x, o);
        if (lane >= o) x += y;
    }
    if (lane == 31) wsum[wrp] = x;
    __syncthreads();
    if (wrp == 0 && lane < 8) {
        int s = wsum[lane], xs = s;
        #pragma unroll
        for (int o = 1; o < 8; o <<= 1) {
            int y = __shfl_up_sync(0xffu, xs, o);
            if (lane >= o) xs += y;
        }
        wsum[lane] = xs - s;
    }
    __syncthreads();
    int ex = g_bsum[blockIdx.x] + wsum[wrp] + (x - tot);
    if (base + 0 < kN) { g_ptr[base + 0] = ex;                g_cnt[base + 0] = 0; }
    if (base + 1 < kN) { g_ptr[base + 1] = ex + v0;           g_cnt[base + 1] = 0; }
    if (base + 2 < kN) { g_ptr[base + 2] = ex + v0 + v1;      g_cnt[base + 2] = 0; }
    if (base + 3 < kN) { g_ptr[base + 3] = ex + v0 + v1 + v2; g_cnt[base + 3] = 0; }
}

// fill CSR + initialize A=1, normA=0.25 in slot order
__global__ void k_fill(const int* __restrict__ h, const int* __restrict__ t) {
    int e = blockIdx.x * blockDim.x + threadIdx.x;
    if (e >= kE) return;
    int hn   = h[e];
    int slot = g_ptr[hn] + atomicAdd(&g_cnt[hn], 1);
    g_csr_t[slot] = t[e];
    reinterpret_cast<float4*>(g_A)[slot]     = make_float4(1.f, 1.f, 1.f, 1.f);
    reinterpret_cast<float4*>(g_normA)[slot] = make_float4(.25f, .25f, .25f, .25f);
}

// initial dinv: normA = 0.25 everywhere -> dval = 0.25 * deg
__global__ void k_dinv0() {
    int n = blockIdx.x * blockDim.x + threadIdx.x;
    if (n >= kN) return;
    float dval = 0.25f * (float)(g_ptr[n + 1] - g_ptr[n]);
    float di = rsqrtf(fmaxf(dval, 1e-8f));
    reinterpret_cast<float4*>(g_dinvA)[n] = make_float4(di, di, di, di);
}

// ---------------- per-layer: tanh(normalized tail chunks) + optional egoS ----------------
__global__ void k_tail(int sel, int wegos) {
    const float* ego = sel ? g_buf1 : g_buf0;
    int i = blockIdx.x * blockDim.x + threadIdx.x;   // (node, factor)
    if (i >= kN * 4) return;
    const float4* src = reinterpret_cast<const float4*>(ego) + i * 4;
    float4 v0 = src[0], v1 = src[1], v2 = src[2], v3 = src[3];
    float ss = v0.x*v0.x + v0.y*v0.y + v0.z*v0.z + v0.w*v0.w
             + v1.x*v1.x + v1.y*v1.y + v1.z*v1.z + v1.w*v1.w
             + v2.x*v2.x + v2.y*v2.y + v2.z*v2.z + v2.w*v2.w
             + v3.x*v3.x + v3.y*v3.y + v3.z*v3.z + v3.w*v3.w;
    float inv = 1.0f / fmaxf(sqrtf(ss), 1e-12f);
    float4* dst = reinterpret_cast<float4*>(g_Tn) + i * 4;
    dst[0] = make_float4(tanhf(v0.x*inv), tanhf(v0.y*inv), tanhf(v0.z*inv), tanhf(v0.w*inv));
    dst[1] = make_float4(tanhf(v1.x*inv), tanhf(v1.y*inv), tanhf(v1.z*inv), tanhf(v1.w*inv));
    dst[2] = make_float4(tanhf(v2.x*inv), tanhf(v2.y*inv), tanhf(v2.z*inv), tanhf(v2.w*inv));
    dst[3] = make_float4(tanhf(v3.x*inv), tanhf(v3.y*inv), tanhf(v3.z*inv), tanhf(v3.w*inv));
    if (wegos) {
        float di = g_dinvA[i];
        float4* ds = reinterpret_cast<float4*>(g_egoS0) + i * 4;
        ds[0] = make_float4(v0.x*di, v0.y*di, v0.z*di, v0.w*di);
        ds[1] = make_float4(v1.x*di, v1.y*di, v1.z*di, v1.w*di);
        ds[2] = make_float4(v2.x*di, v2.y*di, v2.z*di, v2.w*di);
        ds[3] = make_float4(v3.x*di, v3.y*di, v3.z*di, v3.w*di);
    }
}

// ---------------- fused iteration ----------------
// one warp per node; lane owns dims [2*lane, 2*lane+1]; factor f = lane>>3.
// MP gathers prescaled egoS (read from esel buffer, written to the OTHER one —
// double-buffered so concurrent warps never observe next-iteration scaling).
// mode: 0 = routing, epilogue writes egoS_next = ego[w]*dinvN
//       1 = routing, epilogue writes egoS_next = acc*dinvN (layer transition)
//       2 = final output, no routing
__global__ void __launch_bounds__(256) k_fused(
        int sel_in, int dsel, int esel, int mode,
        const float* __restrict__ user, const float* __restrict__ item,
        float* __restrict__ out)
{
    __shared__ int    sm_t[8][32];
    __shared__ float  sm_wT[8][4][33];
    __shared__ float2 sm_h[8][32];      // normalized head (64 floats / warp)

    const int warp = threadIdx.x >> 5;
    const int lane = threadIdx.x & 31;
    const int w = blockIdx.x * 8 + warp;
    const int f = lane >> 3;

    const float*  ego    = sel_in ? g_buf1 : g_buf0;
    float*        fe     = sel_in ? g_buf0 : g_buf1;
    const float2* egoS   = reinterpret_cast<const float2*>(esel ? g_egoS1 : g_egoS0);
    float2*       egoSN  = reinterpret_cast<float2*>(esel ? g_egoS0 : g_egoS1);
    const float4* dinvC  = reinterpret_cast<const float4*>(dsel ? g_dinvB : g_dinvA);
    float4*       dinvN  = reinterpret_cast<float4*>(dsel ? g_dinvA : g_dinvB);
    const float4* normA  = reinterpret_cast<const float4*>(g_normA);
    float4*       normAo = reinterpret_cast<float4*>(g_normA);
    float4*       Ap     = reinterpret_cast<float4*>(g_A);

    const int s = g_ptr[w], e = g_ptr[w + 1];

    // ---- message passing ----
    float2 acc = make_float2(0.f, 0.f);
    for (int base = s; base < e; base += 32) {
        int j = base + lane;
        bool valid = j < e;
        int t = valid ? g_csr_t[j] : 0;
        float4 na = valid ? normA[j] : make_float4(0.f, 0.f, 0.f, 0.f);
        sm_t[warp][lane] = t;
        sm_wT[warp][0][lane] = na.x;
        sm_wT[warp][1][lane] = na.y;
        sm_wT[warp][2][lane] = na.z;
        sm_wT[warp][3][lane] = na.w;
        __syncwarp();
        int cnt = min(32, e - base);
        #pragma unroll 8
        for (int k = 0; k < cnt; k++) {
            int   tk = sm_t[warp][k];
            float wk = sm_wT[warp][f][k];
            float2 ev = egoS[tk * 32 + lane];
            acc.x += wk * ev.x;
            acc.y += wk * ev.y;
        }
        __syncwarp();
    }
    {
        float4 dh = dinvC[w];
        float ds = (f == 0) ? dh.x : (f == 1) ? dh.y : (f == 2) ? dh.z : dh.w;
        acc.x *= ds; acc.y *= ds;
    }

    if (mode == 2) {
        // final: out = (input_ego + prev_layer(ego buf) + fe)/3
        const float* inp = (w < kNUser) ? user + (size_t)w * kD : item + (size_t)(w - kNUser) * kD;
        float2 a = reinterpret_cast<const float2*>(inp)[lane];
        float2 b = reinterpret_cast<const float2*>(ego + w * kD)[lane];
        float2 o;
        o.x = (a.x + b.x + acc.x) * (1.0f / 3.0f);
        o.y = (a.y + b.y + acc.y) * (1.0f / 3.0f);
        reinterpret_cast<float2*>(out + w * kD)[lane] = o;
        return;
    }

    reinterpret_cast<float2*>(fe + w * kD)[lane] = acc;

    // ---- head inverse norm (per 8-lane group = one factor) ----
    float ss = acc.x * acc.x + acc.y * acc.y;
    #pragma unroll
    for (int o = 4; o >= 1; o >>= 1) ss += __shfl_xor_sync(0xffffffffu, ss, o);
    const float hinv = 1.0f / fmaxf(sqrtf(ss), 1e-12f);
    sm_h[warp][lane] = make_float2(acc.x * hinv, acc.y * hinv);
    __syncwarp();

    // ---- routing: lane-per-edge, fused softmax + dval accumulation ----
    const float4* hp = reinterpret_cast<const float4*>(&sm_h[warp][0]);
    float4 dval = make_float4(0.f, 0.f, 0.f, 0.f);
    for (int base = s; base < e; base += 32) {
        int j = base + lane;
        if (j < e) {
            int t = g_csr_t[j];
            const float4* tn = reinterpret_cast<const float4*>(g_Tn + t * kD);
            float q0 = 0.f, q1 = 0.f, q2 = 0.f, q3 = 0.f;
            #pragma unroll
            for (int c = 0; c < 4; c++) {
                float4 h0 = hp[c],      t0 = tn[c];
                float4 h1 = hp[4 + c],  t1 = tn[4 + c];
                float4 h2 = hp[8 + c],  t2 = tn[8 + c];
                float4 h3 = hp[12 + c], t3 = tn[12 + c];
                q0 += h0.x*t0.x + h0.y*t0.y + h0.z*t0.z + h0.w*t0.w;
                q1 += h1.x*t1.x + h1.y*t1.y + h1.z*t1.z + h1.w*t1.w;
                q2 += h2.x*t2.x + h2.y*t2.y + h2.z*t2.z + h2.w*t2.w;
                q3 += h3.x*t3.x + h3.y*t3.y + h3.z*t3.z + h3.w*t3.w;
            }
            float4 An = Ap[j];
            An.x += q0; An.y += q1; An.z += q2; An.w += q3;
            float m  = fmaxf(fmaxf(An.x, An.y), fmaxf(An.z, An.w));
            float e0 = __expf(An.x - m), e1 = __expf(An.y - m);
            float e2 = __expf(An.z - m), e3 = __expf(An.w - m);
            float inv = 1.0f / (e0 + e1 + e2 + e3);
            Ap[j] = An;
            float4 nA = make_float4(e0 * inv, e1 * inv, e2 * inv, e3 * inv);
            normAo[j] = nA;
            dval.x += nA.x; dval.y += nA.y; dval.z += nA.z; dval.w += nA.w;
        }
    }
    // reduce dval across warp -> next iteration's dinv for this node (all lanes)
    #pragma unroll
    for (int o = 16; o >= 1; o >>= 1) {
        dval.x += __shfl_xor_sync(0xffffffffu, dval.x, o);
        dval.y += __shfl_xor_sync(0xffffffffu, dval.y, o);
        dval.z += __shfl_xor_sync(0xffffffffu, dval.z, o);
        dval.w += __shfl_xor_sync(0xffffffffu, dval.w, o);
    }
    float4 dN = make_float4(rsqrtf(fmaxf(dval.x, 1e-8f)),
                            rsqrtf(fmaxf(dval.y, 1e-8f)),
                            rsqrtf(fmaxf(dval.z, 1e-8f)),
                            rsqrtf(fmaxf(dval.w, 1e-8f)));
    if (lane == 0) dinvN[w] = dN;

    // write next iteration's prescaled ego row (to the OTHER egoS buffer)
    float2 src;
    if (mode == 1) {
        src = acc;                                        // next layer's ego == fe just computed
    } else {
        src = reinterpret_cast<const float2*>(ego + w * kD)[lane];   // same-layer ego
    }
    float dNf = (f == 0) ? dN.x : (f == 1) ? dN.y : (f == 2) ? dN.z : dN.w;
    egoSN[w * 32 + lane] = make_float2(src.x * dNf, src.y * dNf);
}

// ---------------- host driver ----------------
extern "C" void kernel_launch(void* const* d_in, const int* in_sizes, int n_in,
                              void* d_out, int out_size) {
    const float* user = (const float*)d_in[0];
    const float* item = (const float*)d_in[1];
    const int*   hl   = (const int*)d_in[2];
    const int*   tl   = (const int*)d_in[3];
    float* out = (float*)d_out;

    const int TB = 256;
    k_init_ego<<<(kN * kD + TB - 1) / TB, TB>>>(user, item);
    k_zero_cnt<<<(kN + TB - 1) / TB, TB>>>();
    k_count<<<(kE + TB - 1) / TB, TB>>>(hl);
    k_chunk_reduce<<<kNChunk, TB>>>();
    k_bsum_scan<<<1, 32>>>();
    k_chunk_scan<<<kNChunk, TB>>>();
    k_fill<<<(kE + TB - 1) / TB, TB>>>(hl, tl);
    k_dinv0<<<(kN + TB - 1) / TB, TB>>>();

    const int FG = kN / 8;   // 8 warps / block, kN divisible by 8
    // layer 0: ego=buf0 -> fe=buf1
    k_tail<<<(kN * 4 + TB - 1) / TB, TB>>>(0, 1);        // Tn + egoS0 = buf0 * dinvA(init)
    k_fused<<<FG, TB>>>(0, 0, 0, 0, user, item, out);    // reads egoS0,dinvA; writes dinvB, egoS1=buf0*dinvB
    k_fused<<<FG, TB>>>(0, 1, 1, 1, user, item, out);    // reads egoS1,dinvB; writes dinvA, egoS0=fe*dinvA
    // layer 1: ego=buf1 -> fe=buf0
    k_tail<<<(kN * 4 + TB - 1) / TB, TB>>>(1, 0);        // Tn only (egoS0 already written)
    k_fused<<<FG, TB>>>(1, 0, 0, 0, user, item, out);    // reads egoS0,dinvA; writes dinvB, egoS1=buf1*dinvB
    k_fused<<<FG, TB>>>(1, 1, 1, 2, user, item, out);    // final: reads egoS1,dinvB
    (void)in_sizes; (void)n_in; (void)out_size;
}

// round 6
// speedup vs baseline: 1.8242x; 1.0692x over previous
#include <cuda_runtime.h>
#include <cuda_bf16.h>

namespace {
constexpr int kNUser = 50000;
constexpr int kN     = 80000;      // total nodes
constexpr int kE     = 1000000;    // 2 * NNZ symmetric edges
constexpr int kD     = 64;
constexpr int kChunk = 1024;
constexpr int kNChunk = (kN + kChunk - 1) / kChunk;   // 79
}

// ---------------- device scratch (static, no allocation) ----------------
__device__ float g_A[kE * 4];         // routing logits, CSR-slot order
__device__ float g_normA[kE * 4];     // softmax(A), CSR-slot order
__device__ float g_buf0[kN * kD];     // initial ego (layer-0 input; never overwritten)
__device__ float g_buf1[kN * kD];     // layer-0 output = layer-1 input
__device__ float g_egoS[kN * kD];     // layer ego prescaled by current dinv
__device__ float g_Tn[kN * kD];       // tanh(normalized tail chunks), per layer
__device__ float g_dinvA[kN * 4];     // 1/sqrt(degree-weight), ping
__device__ float g_dinvB[kN * 4];     // pong
__device__ int   g_ptr[kN + 1];       // CSR row pointers (by head)
__device__ int   g_cnt[kN];           // histogram / fill counters
__device__ int   g_csr_t[kE];         // tail node per CSR slot
__device__ int   g_bsum[kNChunk];     // per-chunk sums for multi-block scan

// ---------------- init ----------------
__global__ void k_init_ego(const float* __restrict__ user, const float* __restrict__ item) {
    int i = blockIdx.x * blockDim.x + threadIdx.x;
    if (i >= kN * kD) return;
    g_buf0[i] = (i < kNUser * kD) ? user[i] : item[i - kNUser * kD];
}

__global__ void k_zero_cnt() {
    int i = blockIdx.x * blockDim.x + threadIdx.x;
    if (i < kN) g_cnt[i] = 0;
}

// ---------------- CSR build ----------------
__global__ void k_count(const int* __restrict__ h) {
    int e = blockIdx.x * blockDim.x + threadIdx.x;
    if (e >= kE) return;
    atomicAdd(&g_cnt[h[e]], 1);
}

__global__ void k_chunk_reduce() {            // kNChunk blocks x 256
    __shared__ int wsum[8];
    const int lane = threadIdx.x & 31, wrp = threadIdx.x >> 5;
    int base = blockIdx.x * kChunk + (int)threadIdx.x * 4;
    int s = 0;
    #pragma unroll
    for (int k = 0; k < 4; k++) { int i = base + k; if (i < kN) s += g_cnt[i]; }
    #pragma unroll
    for (int o = 16; o >= 1; o >>= 1) s += __shfl_xor_sync(0xffffffffu, s, o);
    if (lane == 0) wsum[wrp] = s;
    __syncthreads();
    if (threadIdx.x == 0) {
        int t = 0;
        #pragma unroll
        for (int k = 0; k < 8; k++) t += wsum[k];
        g_bsum[blockIdx.x] = t;
    }
}

__global__ void k_bsum_scan() {               // 1 block x 32
    const int lane = threadIdx.x;
    int carry = 0;
    for (int base = 0; base < kNChunk; base += 32) {
        int i = base + lane;
        int v = (i < kNChunk) ? g_bsum[i] : 0;
        int x = v;
        #pragma unroll
        for (int o = 1; o < 32; o <<= 1) {
            int y = __shfl_up_sync(0xffffffffu, x, o);
            if (lane >= o) x += y;
        }
        if (i < kNChunk) g_bsum[i] = carry + x - v;     // exclusive
        carry += __shfl_sync(0xffffffffu, x, 31);
    }
    if (lane == 0) g_ptr[kN] = carry;
}

__global__ void k_chunk_scan() {              // kNChunk blocks x 256
    __shared__ int wsum[8];
    const int lane = threadIdx.x & 31, wrp = threadIdx.x >> 5;
    int base = blockIdx.x * kChunk + (int)threadIdx.x * 4;
    int v0 = 0, v1 = 0, v2 = 0, v3 = 0;
    if (base + 3 < kN) {
        int4 v = *reinterpret_cast<const int4*>(&g_cnt[base]);
        v0 = v.x; v1 = v.y; v2 = v.z; v3 = v.w;
    } else {
        if (base + 0 < kN) v0 = g_cnt[base + 0];
        if (base + 1 < kN) v1 = g_cnt[base + 1];
        if (base + 2 < kN) v2 = g_cnt[base + 2];
        if (base + 3 < kN) v3 = g_cnt[base + 3];
    }
    int tot = v0 + v1 + v2 + v3;
    int x = tot;
    #pragma unroll
    for (int o = 1; o < 32; o <<= 1) {
        int y = __shfl_up_sync(0xffffffffu, x, o);
        if (lane >= o) x += y;
    }
    if (lane == 31) wsum[wrp] = x;
    __syncthreads();
    if (wrp == 0 && lane < 8) {
        int s = wsum[lane], xs = s;
        #pragma unroll
        for (int o = 1; o < 8; o <<= 1) {
            int y = __shfl_up_sync(0xffu, xs, o);
            if (lane >= o) xs += y;
        }
        wsum[lane] = xs - s;
    }
    __syncthreads();
    int ex = g_bsum[blockIdx.x] + wsum[wrp] + (x - tot);
    if (base + 0 < kN) { g_ptr[base + 0] = ex;                g_cnt[base + 0] = 0; }
    if (base + 1 < kN) { g_ptr[base + 1] = ex + v0;           g_cnt[base + 1] = 0; }
    if (base + 2 < kN) { g_ptr[base + 2] = ex + v0 + v1;      g_cnt[base + 2] = 0; }
    if (base + 3 < kN) { g_ptr[base + 3] = ex + v0 + v1 + v2; g_cnt[base + 3] = 0; }
}

// fill CSR + initialize A=1, normA=0.25 in slot order
__global__ void k_fill(const int* __restrict__ h, const int* __restrict__ t) {
    int e = blockIdx.x * blockDim.x + threadIdx.x;
    if (e >= kE) return;
    int hn   = h[e];
    int slot = g_ptr[hn] + atomicAdd(&g_cnt[hn], 1);
    g_csr_t[slot] = t[e];
    reinterpret_cast<float4*>(g_A)[slot]     = make_float4(1.f, 1.f, 1.f, 1.f);
    reinterpret_cast<float4*>(g_normA)[slot] = make_float4(.25f, .25f, .25f, .25f);
}

// initial dinv: normA = 0.25 everywhere -> dval = 0.25 * deg
__global__ void k_dinv0() {
    int n = blockIdx.x * blockDim.x + threadIdx.x;
    if (n >= kN) return;
    float dval = 0.25f * (float)(g_ptr[n + 1] - g_ptr[n]);
    float di = rsqrtf(fmaxf(dval, 1e-8f));
    reinterpret_cast<float4*>(g_dinvA)[n] = make_float4(di, di, di, di);
}

// ---------------- per-layer: tanh(normalized tail chunks) + egoS = ego*dinvA ----------------
__global__ void k_tail(int sel) {
    const float* ego = sel ? g_buf1 : g_buf0;
    int i = blockIdx.x * blockDim.x + threadIdx.x;   // (node, factor)
    if (i >= kN * 4) return;
    const float4* src = reinterpret_cast<const float4*>(ego) + i * 4;
    float4 v0 = src[0], v1 = src[1], v2 = src[2], v3 = src[3];
    float ss = v0.x*v0.x + v0.y*v0.y + v0.z*v0.z + v0.w*v0.w
             + v1.x*v1.x + v1.y*v1.y + v1.z*v1.z + v1.w*v1.w
             + v2.x*v2.x + v2.y*v2.y + v2.z*v2.z + v2.w*v2.w
             + v3.x*v3.x + v3.y*v3.y + v3.z*v3.z + v3.w*v3.w;
    float inv = 1.0f / fmaxf(sqrtf(ss), 1e-12f);
    float4* dst = reinterpret_cast<float4*>(g_Tn) + i * 4;
    dst[0] = make_float4(tanhf(v0.x*inv), tanhf(v0.y*inv), tanhf(v0.z*inv), tanhf(v0.w*inv));
    dst[1] = make_float4(tanhf(v1.x*inv), tanhf(v1.y*inv), tanhf(v1.z*inv), tanhf(v1.w*inv));
    dst[2] = make_float4(tanhf(v2.x*inv), tanhf(v2.y*inv), tanhf(v2.z*inv), tanhf(v2.w*inv));
    dst[3] = make_float4(tanhf(v3.x*inv), tanhf(v3.y*inv), tanhf(v3.z*inv), tanhf(v3.w*inv));
    float di = g_dinvA[i];
    float4* ds = reinterpret_cast<float4*>(g_egoS) + i * 4;
    ds[0] = make_float4(v0.x*di, v0.y*di, v0.z*di, v0.w*di);
    ds[1] = make_float4(v1.x*di, v1.y*di, v1.z*di, v1.w*di);
    ds[2] = make_float4(v2.x*di, v2.y*di, v2.z*di, v2.w*di);
    ds[3] = make_float4(v3.x*di, v3.y*di, v3.z*di, v3.w*di);
}

// ---------------- between iterations: egoS = ego * dinvB (coalesced) ----------------
__global__ void k_rescale(int sel) {
    const float* ego = sel ? g_buf1 : g_buf0;
    int i = blockIdx.x * blockDim.x + threadIdx.x;   // (node, factor)
    if (i >= kN * 4) return;
    const float4* src = reinterpret_cast<const float4*>(ego) + i * 4;
    float di = g_dinvB[i];
    float4* ds = reinterpret_cast<float4*>(g_egoS) + i * 4;
    float4 v0 = src[0], v1 = src[1], v2 = src[2], v3 = src[3];
    ds[0] = make_float4(v0.x*di, v0.y*di, v0.z*di, v0.w*di);
    ds[1] = make_float4(v1.x*di, v1.y*di, v1.z*di, v1.w*di);
    ds[2] = make_float4(v2.x*di, v2.y*di, v2.z*di, v2.w*di);
    ds[3] = make_float4(v3.x*di, v3.y*di, v3.z*di, v3.w*di);
}

// ---------------- fused iteration ----------------
// one warp per node; lane owns dims [2*lane, 2*lane+1]; factor f = lane>>3.
// MP gathers prescaled egoS. egoS is NEVER written here (k_rescale/k_tail own it).
// mode: 0 = routing, fe NOT written (mid-layer iteration)
//       1 = routing + fe write (layer output)
//       2 = final output (out = (buf0 + ego + acc)/3), no routing
__global__ void __launch_bounds__(256) k_fused(
        int sel_in, int dsel, int mode, float* __restrict__ out)
{
    __shared__ int    sm_t[8][32];
    __shared__ float  sm_wT[8][4][33];
    __shared__ float2 sm_h[8][32];      // normalized head (64 floats / warp)

    const int warp = threadIdx.x >> 5;
    const int lane = threadIdx.x & 31;
    const int w = blockIdx.x * 8 + warp;
    const int f = lane >> 3;

    const float*  ego    = sel_in ? g_buf1 : g_buf0;
    float*        fe     = sel_in ? g_buf0 : g_buf1;   // only used in mode 1 (sel_in=0)
    const float2* egoS   = reinterpret_cast<const float2*>(g_egoS);
    const float4* dinvC  = reinterpret_cast<const float4*>(dsel ? g_dinvB : g_dinvA);
    float4*       dinvN  = reinterpret_cast<float4*>(dsel ? g_dinvA : g_dinvB);
    const float4* normA  = reinterpret_cast<const float4*>(g_normA);
    float4*       normAo = reinterpret_cast<float4*>(g_normA);
    float4*       Ap     = reinterpret_cast<float4*>(g_A);

    const int s = g_ptr[w], e = g_ptr[w + 1];

    // ---- message passing ----
    float2 acc = make_float2(0.f, 0.f);
    for (int base = s; base < e; base += 32) {
        int j = base + lane;
        bool valid = j < e;
        int t = valid ? g_csr_t[j] : 0;
        float4 na = valid ? normA[j] : make_float4(0.f, 0.f, 0.f, 0.f);
        sm_t[warp][lane] = t;
        sm_wT[warp][0][lane] = na.x;
        sm_wT[warp][1][lane] = na.y;
        sm_wT[warp][2][lane] = na.z;
        sm_wT[warp][3][lane] = na.w;
        __syncwarp();
        int cnt = min(32, e - base);
        #pragma unroll 8
        for (int k = 0; k < cnt; k++) {
            int   tk = sm_t[warp][k];
            float wk = sm_wT[warp][f][k];
            float2 ev = egoS[tk * 32 + lane];
            acc.x += wk * ev.x;
            acc.y += wk * ev.y;
        }
        __syncwarp();
    }
    {
        float4 dh = dinvC[w];
        float ds = (f == 0) ? dh.x : (f == 1) ? dh.y : (f == 2) ? dh.z : dh.w;
        acc.x *= ds; acc.y *= ds;
    }

    if (mode == 2) {
        // final: out = (initial_ego(buf0) + layer1_input(ego=buf1) + fe)/3
        float2 a = reinterpret_cast<const float2*>(g_buf0 + w * kD)[lane];
        float2 b = reinterpret_cast<const float2*>(ego + w * kD)[lane];
        float2 o;
        o.x = (a.x + b.x + acc.x) * (1.0f / 3.0f);
        o.y = (a.y + b.y + acc.y) * (1.0f / 3.0f);
        reinterpret_cast<float2*>(out + w * kD)[lane] = o;
        return;
    }

    if (mode == 1)
        reinterpret_cast<float2*>(fe + w * kD)[lane] = acc;

    // ---- head inverse norm (per 8-lane group = one factor) ----
    float ss = acc.x * acc.x + acc.y * acc.y;
    #pragma unroll
    for (int o = 4; o >= 1; o >>= 1) ss += __shfl_xor_sync(0xffffffffu, ss, o);
    const float hinv = 1.0f / fmaxf(sqrtf(ss), 1e-12f);
    sm_h[warp][lane] = make_float2(acc.x * hinv, acc.y * hinv);
    __syncwarp();

    // ---- routing: lane-per-edge, fused softmax + dval accumulation ----
    const float4* hp = reinterpret_cast<const float4*>(&sm_h[warp][0]);
    float4 dval = make_float4(0.f, 0.f, 0.f, 0.f);
    for (int base = s; base < e; base += 32) {
        int j = base + lane;
        if (j < e) {
            int t = g_csr_t[j];
            const float4* tn = reinterpret_cast<const float4*>(g_Tn + t * kD);
            float q0 = 0.f, q1 = 0.f, q2 = 0.f, q3 = 0.f;
            #pragma unroll
            for (int c = 0; c < 4; c++) {
                float4 h0 = hp[c],      t0 = tn[c];
                float4 h1 = hp[4 + c],  t1 = tn[4 + c];
                float4 h2 = hp[8 + c],  t2 = tn[8 + c];
                float4 h3 = hp[12 + c], t3 = tn[12 + c];
                q0 += h0.x*t0.x + h0.y*t0.y + h0.z*t0.z + h0.w*t0.w;
                q1 += h1.x*t1.x + h1.y*t1.y + h1.z*t1.z + h1.w*t1.w;
                q2 += h2.x*t2.x + h2.y*t2.y + h2.z*t2.z + h2.w*t2.w;
                q3 += h3.x*t3.x + h3.y*t3.y + h3.z*t3.z + h3.w*t3.w;
            }
            float4 An = Ap[j];
            An.x += q0; An.y += q1; An.z += q2; An.w += q3;
            float m  = fmaxf(fmaxf(An.x, An.y), fmaxf(An.z, An.w));
            float e0 = __expf(An.x - m), e1 = __expf(An.y - m);
            float e2 = __expf(An.z - m), e3 = __expf(An.w - m);
            float inv = 1.0f / (e0 + e1 + e2 + e3);
            Ap[j] = An;
            float4 nA = make_float4(e0 * inv, e1 * inv, e2 * inv, e3 * inv);
            normAo[j] = nA;
            dval.x += nA.x; dval.y += nA.y; dval.z += nA.z; dval.w += nA.w;
        }
    }
    // reduce dval across warp -> next iteration's dinv for this node
    #pragma unroll
    for (int o = 16; o >= 1; o >>= 1) {
        dval.x += __shfl_xor_sync(0xffffffffu, dval.x, o);
        dval.y += __shfl_xor_sync(0xffffffffu, dval.y, o);
        dval.z += __shfl_xor_sync(0xffffffffu, dval.z, o);
        dval.w += __shfl_xor_sync(0xffffffffu, dval.w, o);
    }
    if (lane == 0) {
        dinvN[w] = make_float4(rsqrtf(fmaxf(dval.x, 1e-8f)),
                               rsqrtf(fmaxf(dval.y, 1e-8f)),
                               rsqrtf(fmaxf(dval.z, 1e-8f)),
                               rsqrtf(fmaxf(dval.w, 1e-8f)));
    }
}

// ---------------- host driver ----------------
extern "C" void kernel_launch(void* const* d_in, const int* in_sizes, int n_in,
                              void* d_out, int out_size) {
    const float* user = (const float*)d_in[0];
    const float* item = (const float*)d_in[1];
    const int*   hl   = (const int*)d_in[2];
    const int*   tl   = (const int*)d_in[3];
    float* out = (float*)d_out;

    const int TB = 256;
    k_init_ego<<<(kN * kD + TB - 1) / TB, TB>>>(user, item);
    k_zero_cnt<<<(kN + TB - 1) / TB, TB>>>();
    k_count<<<(kE + TB - 1) / TB, TB>>>(hl);
    k_chunk_reduce<<<kNChunk, TB>>>();
    k_bsum_scan<<<1, 32>>>();
    k_chunk_scan<<<kNChunk, TB>>>();
    k_fill<<<(kE + TB - 1) / TB, TB>>>(hl, tl);
    k_dinv0<<<(kN + TB - 1) / TB, TB>>>();

    const int FG = kN / 8;   // 8 warps / block
    const int RG = (kN * 4 + TB - 1) / TB;
    // layer 0: ego=buf0 -> fe=buf1
    k_tail<<<RG, TB>>>(0);                      // Tn(buf0), egoS = buf0*dinvA(init)
    k_fused<<<FG, TB>>>(0, 0, 0, out);          // it0: reads dinvA, writes dinvB; no fe
    k_rescale<<<RG, TB>>>(0);                   // egoS = buf0*dinvB
    k_fused<<<FG, TB>>>(0, 1, 1, out);          // it1: reads dinvB, writes dinvA; fe->buf1
    // layer 1: ego=buf1 -> out
    k_tail<<<RG, TB>>>(1);                      // Tn(buf1), egoS = buf1*dinvA
    k_fused<<<FG, TB>>>(1, 0, 0, out);          // it0: reads dinvA, writes dinvB; no fe
    k_rescale<<<RG, TB>>>(1);                   // egoS = buf1*dinvB
    k_fused<<<FG, TB>>>(1, 1, 2, out);          // final: reads dinvB, no routing
    (void)in_sizes; (void)n_in; (void)out_size;
}

// round 7
// speedup vs baseline: 2.1642x; 1.1864x over previous
#include <cuda_runtime.h>
#include <cuda_fp16.h>
#include <cuda_bf16.h>

namespace {
constexpr int kNUser = 50000;
constexpr int kN     = 80000;      // total nodes
constexpr int kE     = 1000000;    // 2 * NNZ symmetric edges
constexpr int kD     = 64;
constexpr int kChunk = 1024;
constexpr int kNChunk = (kN + kChunk - 1) / kChunk;   // 79
}

// ---------------- device scratch (static, no allocation) ----------------
__device__ float g_A[kE * 4];         // routing logits, CSR-slot order
__device__ float g_normA[kE * 4];     // softmax(A), CSR-slot order
__device__ float g_buf0[kN * kD];     // initial ego (layer-0 input; never overwritten)
__device__ float g_buf1[kN * kD];     // layer-0 output = layer-1 input
__device__ float g_egoS[kN * kD];     // layer ego prescaled by current dinv (fp32)
__device__ uint4 g_TnV[kN * 8];       // tanh(normalized tail chunks), fp16, 128B/node
__device__ float g_dinvA[kN * 4];     // 1/sqrt(degree-weight), ping
__device__ float g_dinvB[kN * 4];     // pong
__device__ int   g_ptr[kN + 1];       // CSR row pointers (by head)
__device__ int   g_cnt[kN];           // histogram / fill counters
__device__ int   g_csr_t[kE];         // tail node per CSR slot
__device__ int   g_bsum[kNChunk];     // per-chunk sums for multi-block scan

__device__ __forceinline__ unsigned pack_h2(float a, float b) {
    __half2 h = __floats2half2_rn(a, b);
    return *reinterpret_cast<unsigned*>(&h);
}

// ---------------- init ----------------
__global__ void k_init_ego(const float* __restrict__ user, const float* __restrict__ item) {
    int i = blockIdx.x * blockDim.x + threadIdx.x;
    if (i >= kN * kD) return;
    g_buf0[i] = (i < kNUser * kD) ? user[i] : item[i - kNUser * kD];
}

__global__ void k_zero_cnt() {
    int i = blockIdx.x * blockDim.x + threadIdx.x;
    if (i < kN) g_cnt[i] = 0;
}

// ---------------- CSR build ----------------
__global__ void k_count(const int* __restrict__ h) {
    int e = blockIdx.x * blockDim.x + threadIdx.x;
    if (e >= kE) return;
    atomicAdd(&g_cnt[h[e]], 1);
}

__global__ void k_chunk_reduce() {            // kNChunk blocks x 256
    __shared__ int wsum[8];
    const int lane = threadIdx.x & 31, wrp = threadIdx.x >> 5;
    int base = blockIdx.x * kChunk + (int)threadIdx.x * 4;
    int s = 0;
    #pragma unroll
    for (int k = 0; k < 4; k++) { int i = base + k; if (i < kN) s += g_cnt[i]; }
    #pragma unroll
    for (int o = 16; o >= 1; o >>= 1) s += __shfl_xor_sync(0xffffffffu, s, o);
    if (lane == 0) wsum[wrp] = s;
    __syncthreads();
    if (threadIdx.x == 0) {
        int t = 0;
        #pragma unroll
        for (int k = 0; k < 8; k++) t += wsum[k];
        g_bsum[blockIdx.x] = t;
    }
}

__global__ void k_bsum_scan() {               // 1 block x 32
    const int lane = threadIdx.x;
    int carry = 0;
    for (int base = 0; base < kNChunk; base += 32) {
        int i = base + lane;
        int v = (i < kNChunk) ? g_bsum[i] : 0;
        int x = v;
        #pragma unroll
        for (int o = 1; o < 32; o <<= 1) {
            int y = __shfl_up_sync(0xffffffffu, x, o);
            if (lane >= o) x += y;
        }
        if (i < kNChunk) g_bsum[i] = carry + x - v;     // exclusive
        carry += __shfl_sync(0xffffffffu, x, 31);
    }
    if (lane == 0) g_ptr[kN] = carry;
}

__global__ void k_chunk_scan() {              // kNChunk blocks x 256
    __shared__ int wsum[8];
    const int lane = threadIdx.x & 31, wrp = threadIdx.x >> 5;
    int base = blockIdx.x * kChunk + (int)threadIdx.x * 4;
    int v0 = 0, v1 = 0, v2 = 0, v3 = 0;
    if (base + 3 < kN) {
        int4 v = *reinterpret_cast<const int4*>(&g_cnt[base]);
        v0 = v.x; v1 = v.y; v2 = v.z; v3 = v.w;
    } else {
        if (base + 0 < kN) v0 = g_cnt[base + 0];
        if (base + 1 < kN) v1 = g_cnt[base + 1];
        if (base + 2 < kN) v2 = g_cnt[base + 2];
        if (base + 3 < kN) v3 = g_cnt[base + 3];
    }
    int tot = v0 + v1 + v2 + v3;
    int x = tot;
    #pragma unroll
    for (int o = 1; o < 32; o <<= 1) {
        int y = __shfl_up_sync(0xffffffffu, x, o);
        if (lane >= o) x += y;
    }
    if (lane == 31) wsum[wrp] = x;
    __syncthreads();
    if (wrp == 0 && lane < 8) {
        int s = wsum[lane], xs = s;
        #pragma unroll
        for (int o = 1; o < 8; o <<= 1) {
            int y = __shfl_up_sync(0xffu, xs, o);
            if (lane >= o) xs += y;
        }
        wsum[lane] = xs - s;
    }
    __syncthreads();
    int ex = g_bsum[blockIdx.x] + wsum[wrp] + (x - tot);
    if (base + 0 < kN) { g_ptr[base + 0] = ex;                g_cnt[base + 0] = 0; }
    if (base + 1 < kN) { g_ptr[base + 1] = ex + v0;           g_cnt[base + 1] = 0; }
    if (base + 2 < kN) { g_ptr[base + 2] = ex + v0 + v1;      g_cnt[base + 2] = 0; }
    if (base + 3 < kN) { g_ptr[base + 3] = ex + v0 + v1 + v2; g_cnt[base + 3] = 0; }
}

// fill CSR + initialize A=1, normA=0.25 in slot order
__global__ void k_fill(const int* __restrict__ h, const int* __restrict__ t) {
    int e = blockIdx.x * blockDim.x + threadIdx.x;
    if (e >= kE) return;
    int hn   = h[e];
    int slot = g_ptr[hn] + atomicAdd(&g_cnt[hn], 1);
    g_csr_t[slot] = t[e];
    reinterpret_cast<float4*>(g_A)[slot]     = make_float4(1.f, 1.f, 1.f, 1.f);
    reinterpret_cast<float4*>(g_normA)[slot] = make_float4(.25f, .25f, .25f, .25f);
}

// initial dinv: normA = 0.25 everywhere -> dval = 0.25 * deg
__global__ void k_dinv0() {
    int n = blockIdx.x * blockDim.x + threadIdx.x;
    if (n >= kN) return;
    float dval = 0.25f * (float)(g_ptr[n + 1] - g_ptr[n]);
    float di = rsqrtf(fmaxf(dval, 1e-8f));
    reinterpret_cast<float4*>(g_dinvA)[n] = make_float4(di, di, di, di);
}

// ---------------- per-layer: tanh(normalized tail chunks)->fp16 + egoS = ego*dinvA ----------------
__global__ void k_tail(int sel) {
    const float* ego = sel ? g_buf1 : g_buf0;
    int i = blockIdx.x * blockDim.x + threadIdx.x;   // (node, factor)
    if (i >= kN * 4) return;
    const float4* src = reinterpret_cast<const float4*>(ego) + i * 4;
    float4 v0 = src[0], v1 = src[1], v2 = src[2], v3 = src[3];
    float ss = v0.x*v0.x + v0.y*v0.y + v0.z*v0.z + v0.w*v0.w
             + v1.x*v1.x + v1.y*v1.y + v1.z*v1.z + v1.w*v1.w
             + v2.x*v2.x + v2.y*v2.y + v2.z*v2.z + v2.w*v2.w
             + v3.x*v3.x + v3.y*v3.y + v3.z*v3.z + v3.w*v3.w;
    float inv = 1.0f / fmaxf(sqrtf(ss), 1e-12f);
    uint4 u0, u1;
    u0.x = pack_h2(tanhf(v0.x*inv), tanhf(v0.y*inv));
    u0.y = pack_h2(tanhf(v0.z*inv), tanhf(v0.w*inv));
    u0.z = pack_h2(tanhf(v1.x*inv), tanhf(v1.y*inv));
    u0.w = pack_h2(tanhf(v1.z*inv), tanhf(v1.w*inv));
    u1.x = pack_h2(tanhf(v2.x*inv), tanhf(v2.y*inv));
    u1.y = pack_h2(tanhf(v2.z*inv), tanhf(v2.w*inv));
    u1.z = pack_h2(tanhf(v3.x*inv), tanhf(v3.y*inv));
    u1.w = pack_h2(tanhf(v3.z*inv), tanhf(v3.w*inv));
    g_TnV[i * 2]     = u0;
    g_TnV[i * 2 + 1] = u1;
    float di = g_dinvA[i];
    float4* ds = reinterpret_cast<float4*>(g_egoS) + i * 4;
    ds[0] = make_float4(v0.x*di, v0.y*di, v0.z*di, v0.w*di);
    ds[1] = make_float4(v1.x*di, v1.y*di, v1.z*di, v1.w*di);
    ds[2] = make_float4(v2.x*di, v2.y*di, v2.z*di, v2.w*di);
    ds[3] = make_float4(v3.x*di, v3.y*di, v3.z*di, v3.w*di);
}

// ---------------- between iterations: egoS = ego * dinvB (coalesced) ----------------
__global__ void k_rescale(int sel) {
    const float* ego = sel ? g_buf1 : g_buf0;
    int i = blockIdx.x * blockDim.x + threadIdx.x;   // (node, factor)
    if (i >= kN * 4) return;
    const float4* src = reinterpret_cast<const float4*>(ego) + i * 4;
    float di = g_dinvB[i];
    float4* ds = reinterpret_cast<float4*>(g_egoS) + i * 4;
    float4 v0 = src[0], v1 = src[1], v2 = src[2], v3 = src[3];
    ds[0] = make_float4(v0.x*di, v0.y*di, v0.z*di, v0.w*di);
    ds[1] = make_float4(v1.x*di, v1.y*di, v1.z*di, v1.w*di);
    ds[2] = make_float4(v2.x*di, v2.y*di, v2.z*di, v2.w*di);
    ds[3] = make_float4(v3.x*di, v3.y*di, v3.z*di, v3.w*di);
}

// ---------------- fused iteration ----------------
// one warp per node. MP: lane owns dims [2l,2l+1], factor f = lane>>3,
// smem-staged edge weights, serial gather of egoS rows (warp-contiguous).
// Routing: HALF-WARP per edge; each of the 16 lanes reads 4 dims (8B fp16)
// of the tail's Tn row contiguously -> 1 L1tex line per edge.
// mode: 0 = routing, fe NOT written; 1 = routing + fe write; 2 = final output.
__global__ void __launch_bounds__(256) k_fused(
        int sel_in, int dsel, int mode, float* __restrict__ out)
{
    __shared__ int    sm_t[8][32];
    __shared__ float  sm_wT[8][4][33];
    __shared__ float2 sm_h[8][32];      // normalized head (64 floats / warp)

    const int warp = threadIdx.x >> 5;
    const int lane = threadIdx.x & 31;
    const int w = blockIdx.x * 8 + warp;
    const int f = lane >> 3;

    const float*  ego    = sel_in ? g_buf1 : g_buf0;
    float*        fe     = sel_in ? g_buf0 : g_buf1;   // only written in mode 1 (sel_in=0)
    const float2* egoS   = reinterpret_cast<const float2*>(g_egoS);
    const float4* dinvC  = reinterpret_cast<const float4*>(dsel ? g_dinvB : g_dinvA);
    float4*       dinvN  = reinterpret_cast<float4*>(dsel ? g_dinvA : g_dinvB);
    const float4* normA  = reinterpret_cast<const float4*>(g_normA);

    const int s = g_ptr[w], e = g_ptr[w + 1];

    // ---- message passing ----
    float2 acc = make_float2(0.f, 0.f);
    for (int base = s; base < e; base += 32) {
        int j = base + lane;
        bool valid = j < e;
        int t = valid ? g_csr_t[j] : 0;
        float4 na = valid ? normA[j] : make_float4(0.f, 0.f, 0.f, 0.f);
        sm_t[warp][lane] = t;
        sm_wT[warp][0][lane] = na.x;
        sm_wT[warp][1][lane] = na.y;
        sm_wT[warp][2][lane] = na.z;
        sm_wT[warp][3][lane] = na.w;
        __syncwarp();
        int cnt = min(32, e - base);
        #pragma unroll 8
        for (int k = 0; k < cnt; k++) {
            int   tk = sm_t[warp][k];
            float wk = sm_wT[warp][f][k];
            float2 ev = egoS[tk * 32 + lane];
            acc.x += wk * ev.x;
            acc.y += wk * ev.y;
        }
        __syncwarp();
    }
    {
        float4 dh = dinvC[w];
        float ds = (f == 0) ? dh.x : (f == 1) ? dh.y : (f == 2) ? dh.z : dh.w;
        acc.x *= ds; acc.y *= ds;
    }

    if (mode == 2) {
        // final: out = (initial_ego(buf0) + layer1_input(buf1) + fe)/3
        float2 a = reinterpret_cast<const float2*>(g_buf0 + w * kD)[lane];
        float2 b = reinterpret_cast<const float2*>(ego + w * kD)[lane];
        float2 o;
        o.x = (a.x + b.x + acc.x) * (1.0f / 3.0f);
        o.y = (a.y + b.y + acc.y) * (1.0f / 3.0f);
        reinterpret_cast<float2*>(out + w * kD)[lane] = o;
        return;
    }

    if (mode == 1)
        reinterpret_cast<float2*>(fe + w * kD)[lane] = acc;

    // ---- head inverse norm (per 8-lane group = one factor) ----
    float ss = acc.x * acc.x + acc.y * acc.y;
    #pragma unroll
    for (int o = 4; o >= 1; o >>= 1) ss += __shfl_xor_sync(0xffffffffu, ss, o);
    const float hinv = 1.0f / fmaxf(sqrtf(ss), 1e-12f);
    sm_h[warp][lane] = make_float2(acc.x * hinv, acc.y * hinv);
    __syncwarp();

    // ---- routing: half-warp per edge ----
    // lane = half*16 + r; r owns dims [4r, 4r+3]; factor fr = r>>2.
    const float4* hp4 = reinterpret_cast<const float4*>(&sm_h[warp][0]);
    const int half = lane >> 4;
    const int r    = lane & 15;
    const int fr   = r >> 2;
    const bool fl  = (r & 3) == 0;    // factor-leader lane
    float dv = 0.f;
    for (int b = s; b < e; b += 2) {
        int j = b + half;
        bool valid = j < e;
        int t = valid ? g_csr_t[j] : 0;
        uint2 tv = reinterpret_cast<const uint2*>(g_TnV)[t * 16 + r];
        float4 hv = hp4[r];
        float2 t0 = __half22float2(*reinterpret_cast<__half2*>(&tv.x));
        float2 t1 = __half22float2(*reinterpret_cast<__half2*>(&tv.y));
        float p = hv.x*t0.x + hv.y*t0.y + hv.z*t1.x + hv.w*t1.y;
        p += __shfl_xor_sync(0xffffffffu, p, 1);
        p += __shfl_xor_sync(0xffffffffu, p, 2);
        // lanes r%4==0 hold q for factor fr of edge j
        float An = 0.f;
        if (fl && valid) An = g_A[j * 4 + fr] + p;
        float m = fmaxf(An, __shfl_xor_sync(0xffffffffu, An, 4));
        m = fmaxf(m, __shfl_xor_sync(0xffffffffu, m, 8));
        float ex = __expf(An - m);
        float sm = ex + __shfl_xor_sync(0xffffffffu, ex, 4);
        sm += __shfl_xor_sync(0xffffffffu, sm, 8);
        if (fl && valid) {
            float nA = ex / sm;
            g_A[j * 4 + fr]     = An;
            g_normA[j * 4 + fr] = nA;
            dv += nA;
        }
    }
    // combine halves: lanes {0,4,8,12} then hold total dval per factor
    dv += __shfl_xor_sync(0xffffffffu, dv, 16);
    float d1 = __shfl_sync(0xffffffffu, dv, 4);
    float d2 = __shfl_sync(0xffffffffu, dv, 8);
    float d3 = __shfl_sync(0xffffffffu, dv, 12);
    if (lane == 0) {
        dinvN[w] = make_float4(rsqrtf(fmaxf(dv, 1e-8f)),
                               rsqrtf(fmaxf(d1, 1e-8f)),
                               rsqrtf(fmaxf(d2, 1e-8f)),
                               rsqrtf(fmaxf(d3, 1e-8f)));
    }
}

// ---------------- host driver ----------------
extern "C" void kernel_launch(void* const* d_in, const int* in_sizes, int n_in,
                              void* d_out, int out_size) {
    const float* user = (const float*)d_in[0];
    const float* item = (const float*)d_in[1];
    const int*   hl   = (const int*)d_in[2];
    const int*   tl   = (const int*)d_in[3];
    float* out = (float*)d_out;

    const int TB = 256;
    k_init_ego<<<(kN * kD + TB - 1) / TB, TB>>>(user, item);
    k_zero_cnt<<<(kN + TB - 1) / TB, TB>>>();
    k_count<<<(kE + TB - 1) / TB, TB>>>(hl);
    k_chunk_reduce<<<kNChunk, TB>>>();
    k_bsum_scan<<<1, 32>>>();
    k_chunk_scan<<<kNChunk, TB>>>();
    k_fill<<<(kE + TB - 1) / TB, TB>>>(hl, tl);
    k_dinv0<<<(kN + TB - 1) / TB, TB>>>();

    const int FG = kN / 8;   // 8 warps / block
    const int RG = (kN * 4 + TB - 1) / TB;
    // layer 0: ego=buf0 -> fe=buf1
    k_tail<<<RG, TB>>>(0);                      // Tn(buf0) fp16, egoS = buf0*dinvA(init)
    k_fused<<<FG, TB>>>(0, 0, 0, out);          // it0: reads dinvA, writes dinvB; no fe
    k_rescale<<<RG, TB>>>(0);                   // egoS = buf0*dinvB
    k_fused<<<FG, TB>>>(0, 1, 1, out);          // it1: reads dinvB, writes dinvA; fe->buf1
    // layer 1: ego=buf1 -> out
    k_tail<<<RG, TB>>>(1);                      // Tn(buf1) fp16, egoS = buf1*dinvA
    k_fused<<<FG, TB>>>(1, 0, 0, out);          // it0: reads dinvA, writes dinvB; no fe
    k_rescale<<<RG, TB>>>(1);                   // egoS = buf1*dinvB
    k_fused<<<FG, TB>>>(1, 1, 2, out);          // final: reads dinvB, no routing
    (void)in_sizes; (void)n_in; (void)out_size;
}